// round 13
// baseline (speedup 1.0000x reference)
#include <cuda_runtime.h>
#include <cuda_pipeline.h>
#include <math.h>

#define T 4096
#define H 128
#define HH (H*H)
#define C 128
#define NC (T/C)   // 32
#define L 2
#define GRID 128

typedef unsigned long long u64;
union F2U { u64 u; float2 f; };
union F4U { float4 v; u64 u[2]; };

__device__ __forceinline__ u64 pack2(float a) {
    unsigned int ai = __float_as_uint(a);
    u64 r;
    asm("mov.b64 %0, {%1, %1};" : "=l"(r) : "r"(ai));
    return r;
}
__device__ __forceinline__ void fma2(u64& acc, u64 a, u64 b) {
    asm("fma.rn.f32x2 %0, %1, %2, %0;" : "+l"(acc) : "l"(a), "l"(b));
}

// ---------------- scratch (device globals; no allocation allowed) ------------
__device__ float g_x[T*H];
__device__ float g_q[T*H];
__device__ float g_k[T*H];
__device__ float g_kT[T*H];      // per-chunk transposed K: [c][k][s_local]
__device__ float g_v[T*H];
__device__ float g_Wt[10*HH];    // transposed weights [k][n]
__device__ float g_kvp[4*NC*HH]; // per-(chunk,quarter) KV partial sums
__device__ float g_S[NC*HH];     // state before each chunk
__device__ int   g_rloc[T];
__device__ int   g_cs0[NC];
__device__ int   g_crst[NC];
__device__ int   g_barc;         // grid barrier counter (zero-init)
__device__ int   g_barg;         // grid barrier generation (zero-init)

#define SMA ((2*HH + 2*32*128)*4)           // 160KB: max of all phases

// ---------------- software grid barrier (all 128 blocks co-resident) ---------
__device__ __forceinline__ void gridbar() {
    __syncthreads();
    __threadfence();
    if (threadIdx.x == 0) {
        volatile int* vg = &g_barg;
        int gen = *vg;
        if (atomicAdd(&g_barc, 1) == GRID - 1) {
            g_barc = 0;
            __threadfence();
            atomicAdd(&g_barg, 1);
        } else {
            while (*vg == gen) __nanosleep(32);
        }
    }
    __syncthreads();
}

// ---------------- prep: weight transpose + reset preprocessing ---------------
__global__ void prep_kernel(const float* __restrict__ W_in, const float* __restrict__ W_q,
                            const float* __restrict__ W_k, const float* __restrict__ W_v,
                            const float* __restrict__ W_ff, const float* __restrict__ W_out,
                            const unsigned char* __restrict__ start) {
    int b = blockIdx.x;
    int tid = threadIdx.x;
    if (b < 160) {
        __shared__ float tile[32][33];
        int z = b >> 4, sub = b & 15;
        const float* src;
        switch (z) {
            case 0: src = W_in; break;
            case 1: src = W_q; break;
            case 2: src = W_k; break;
            case 3: src = W_v; break;
            case 4: src = W_q + HH; break;
            case 5: src = W_k + HH; break;
            case 6: src = W_v + HH; break;
            case 7: src = W_ff; break;
            case 8: src = W_ff + HH; break;
            default: src = W_out; break;
        }
        float* dst = g_Wt + z*HH;
        int k0 = (sub >> 2)*32, n0 = (sub & 3)*32;
        int tx = tid & 31, ty = tid >> 5;    // (32,8)
        #pragma unroll
        for (int i = 0; i < 4; i++)
            tile[ty + 8*i][tx] = src[(n0 + ty + 8*i)*H + k0 + tx];
        __syncthreads();
        #pragma unroll
        for (int i = 0; i < 4; i++)
            dst[(k0 + ty + 8*i)*H + n0 + tx] = tile[tx][ty + 8*i];
    } else {
        __shared__ unsigned char f[C];
        int c = b - 160;
        if (tid < C) f[tid] = start[c*C + tid];
        __syncthreads();
        if (tid < C) {
            int r = -1;
            for (int j = tid; j >= 0; --j) { if (f[j]) { r = j; break; } }
            g_rloc[c*C + tid] = r;
            if (tid == C-1) { g_cs0[c] = (r >= 0) ? r : 0; g_crst[c] = (r >= 0) ? 1 : 0; }
        }
    }
}

// ---------------- async-copy helpers -----------------------------------------
__device__ __forceinline__ void cpW(float* Ws, const float* __restrict__ Wt, int tid) {
    #pragma unroll
    for (int it = 0; it < 16; it++) {
        int idx = (tid + it*256) * 4;
        __pipeline_memcpy_async(Ws + idx, Wt + idx, 16);
    }
}
__device__ __forceinline__ void cpA(float* As, const float* __restrict__ A, int tid) {
    #pragma unroll
    for (int it = 0; it < 4; it++) {
        int idx = (tid + it*256) * 4;
        __pipeline_memcpy_async(As + idx, A + idx, 16);
    }
}

// ---------------- packed-f32x2 GEMM microkernel -------------------------------
__device__ __forceinline__ void mm32p(u64 acc[4][2], const float* As, const float* Ws,
                                      int gt, int gs, int klen) {
    #pragma unroll 16
    for (int k = 0; k < klen; k++) {
        F4U w; w.v = *(const float4*)&Ws[k*128 + gs*4];
        #pragma unroll
        for (int i = 0; i < 4; i++) {
            u64 a2 = pack2(As[(gt*4+i)*128 + k]);
            fma2(acc[i][0], a2, w.u[0]);
            fma2(acc[i][1], a2, w.u[1]);
        }
    }
}
__device__ __forceinline__ void zacc(u64 acc[4][2]) {
    #pragma unroll
    for (int i = 0; i < 4; i++) { acc[i][0] = 0ull; acc[i][1] = 0ull; }
}
__device__ __forceinline__ void unpk(const u64 acc[4][2], float o[4][4]) {
    #pragma unroll
    for (int i = 0; i < 4; i++) {
        F2U t0, t1; t0.u = acc[i][0]; t1.u = acc[i][1];
        o[i][0] = t0.f.x; o[i][1] = t0.f.y; o[i][2] = t1.f.x; o[i][3] = t1.f.y;
    }
}

__device__ __forceinline__ float phi_f(float v) {
    return (v > 0.f) ? (1.f + v) : __expf(v);
}

// ================= ONE LAYER, ONE KERNEL (4 phases, 3 grid barriers) =========
template<int FIRST, int LAST>
__global__ __launch_bounds__(256) void layer_kernel(
        const float* __restrict__ A0,
        const float* __restrict__ Wt_in, const float* __restrict__ b_in,
        const float* __restrict__ Wtq, const float* __restrict__ Wtk,
        const float* __restrict__ Wtv,
        const float* __restrict__ Wff, const float* __restrict__ bff,
        const float* __restrict__ Wout, const float* __restrict__ bout,
        float* __restrict__ outp) {
    extern __shared__ float sm[];
    int tid = threadIdx.x;
    int bx = blockIdx.x;
    int gt = tid >> 5, gs = tid & 31;

    // ---------------- Phase Q: [map_in] + QKV  (tile t0 = bx*32) -------------
    {
        float* W0 = sm;
        float* W1 = sm + HH;
        float* As = sm + 2*HH;
        int t0 = bx * 32;

        cpA(As, A0 + t0*H, tid);
        cpW(W0, FIRST ? Wt_in : Wtq, tid);
        __pipeline_commit();                       // g0
        cpW(W1, FIRST ? Wtq : Wtk, tid);
        __pipeline_commit();                       // g1
        __pipeline_wait_prior(1);
        __syncthreads();

        if (FIRST) {   // x = emb @ W_in^T + b_in
            u64 pa[4][2]; zacc(pa);
            mm32p(pa, As, W0, gt, gs, 128);
            float acc[4][4]; unpk(pa, acc);
            __syncthreads();
            cpW(W0, Wtk, tid);
            __pipeline_commit();                   // g2: Wk -> W0
            float4 bb = *(const float4*)&b_in[gs*4];
            #pragma unroll
            for (int i = 0; i < 4; i++) {
                float4 r = make_float4(acc[i][0]+bb.x, acc[i][1]+bb.y,
                                       acc[i][2]+bb.z, acc[i][3]+bb.w);
                *(float4*)&As[(gt*4+i)*128 + gs*4] = r;
                *(float4*)&g_x[(t0 + gt*4+i)*H + gs*4] = r;
            }
            __pipeline_wait_prior(1);              // g1 (Wq) done
            __syncthreads();
            {   // q = phi(x @ Wq^T)   [W1]
                u64 p2[4][2]; zacc(p2);
                mm32p(p2, As, W1, gt, gs, 128);
                float a2[4][4]; unpk(p2, a2);
                #pragma unroll
                for (int i = 0; i < 4; i++)
                    *(float4*)&g_q[(t0 + gt*4+i)*H + gs*4] =
                        make_float4(phi_f(a2[i][0]), phi_f(a2[i][1]),
                                    phi_f(a2[i][2]), phi_f(a2[i][3]));
            }
            __syncthreads();                       // W1 free
            cpW(W1, Wtv, tid);
            __pipeline_commit();                   // g3: Wv -> W1
            __pipeline_wait_prior(1);              // g2 (Wk) done
            __syncthreads();
            {   // k = phi(x @ Wk^T)   [W0]
                u64 p2[4][2]; zacc(p2);
                mm32p(p2, As, W0, gt, gs, 128);
                float a2[4][4]; unpk(p2, a2);
                #pragma unroll
                for (int i = 0; i < 4; i++) {
                    int t = t0 + gt*4 + i;
                    float r[4] = {phi_f(a2[i][0]), phi_f(a2[i][1]),
                                  phi_f(a2[i][2]), phi_f(a2[i][3])};
                    *(float4*)&g_k[t*H + gs*4] = make_float4(r[0],r[1],r[2],r[3]);
                    int cc = t >> 7, sl = t & 127;
                    float* kT = g_kT + cc*HH + sl;
                    #pragma unroll
                    for (int j = 0; j < 4; j++) kT[(gs*4+j)*128] = r[j];
                }
            }
            __pipeline_wait_prior(0);              // g3 (Wv) done
            __syncthreads();
            {   // v = x @ Wv^T        [W1]
                u64 p2[4][2]; zacc(p2);
                mm32p(p2, As, W1, gt, gs, 128);
                float a2[4][4]; unpk(p2, a2);
                #pragma unroll
                for (int i = 0; i < 4; i++)
                    *(float4*)&g_v[(t0 + gt*4+i)*H + gs*4] =
                        make_float4(a2[i][0], a2[i][1], a2[i][2], a2[i][3]);
            }
        } else {
            {   // q = phi(x @ Wq^T)   [W0]
                u64 p2[4][2]; zacc(p2);
                mm32p(p2, As, W0, gt, gs, 128);
                float a2[4][4]; unpk(p2, a2);
                #pragma unroll
                for (int i = 0; i < 4; i++)
                    *(float4*)&g_q[(t0 + gt*4+i)*H + gs*4] =
                        make_float4(phi_f(a2[i][0]), phi_f(a2[i][1]),
                                    phi_f(a2[i][2]), phi_f(a2[i][3]));
            }
            __syncthreads();                       // W0 free
            cpW(W0, Wtv, tid);
            __pipeline_commit();                   // g2: Wv -> W0
            __pipeline_wait_prior(1);              // g1 (Wk) done
            __syncthreads();
            {   // k = phi(x @ Wk^T)   [W1]
                u64 p2[4][2]; zacc(p2);
                mm32p(p2, As, W1, gt, gs, 128);
                float a2[4][4]; unpk(p2, a2);
                #pragma unroll
                for (int i = 0; i < 4; i++) {
                    int t = t0 + gt*4 + i;
                    float r[4] = {phi_f(a2[i][0]), phi_f(a2[i][1]),
                                  phi_f(a2[i][2]), phi_f(a2[i][3])};
                    *(float4*)&g_k[t*H + gs*4] = make_float4(r[0],r[1],r[2],r[3]);
                    int cc = t >> 7, sl = t & 127;
                    float* kT = g_kT + cc*HH + sl;
                    #pragma unroll
                    for (int j = 0; j < 4; j++) kT[(gs*4+j)*128] = r[j];
                }
            }
            __pipeline_wait_prior(0);              // g2 (Wv) done
            __syncthreads();
            {   // v = x @ Wv^T        [W0]
                u64 p2[4][2]; zacc(p2);
                mm32p(p2, As, W0, gt, gs, 128);
                float a2[4][4]; unpk(p2, a2);
                #pragma unroll
                for (int i = 0; i < 4; i++)
                    *(float4*)&g_v[(t0 + gt*4+i)*H + gs*4] =
                        make_float4(a2[i][0], a2[i][1], a2[i][2], a2[i][3]);
            }
        }
    }
    gridbar();

    // ---------------- Phase C: chunk_kv quarter partials ---------------------
    {
        float* Ks = sm;            // [32][128]
        float* Vs = sm + 32*128;
        int c = bx >> 2, qi = bx & 3;
        int s0 = g_cs0[c];
        int base = (c*C + qi*32) * H;
        {
            const float4* K4 = (const float4*)(g_k + base);
            const float4* V4 = (const float4*)(g_v + base);
            float4* Ks4 = (float4*)Ks;
            float4* Vs4 = (float4*)Vs;
            #pragma unroll
            for (int it = 0; it < 4; it++) {
                int idx = tid + it*256;
                int srow = idx >> 5;
                float4 kv4 = K4[idx];
                if (qi*32 + srow < s0) kv4 = make_float4(0.f,0.f,0.f,0.f);
                Ks4[idx] = kv4;
                Vs4[idx] = V4[idx];
            }
        }
        __syncthreads();
        int ty = tid >> 4, tx = tid & 15;
        u64 acc[8][4];
        #pragma unroll
        for (int i = 0; i < 8; i++)
            #pragma unroll
            for (int j = 0; j < 4; j++) acc[i][j] = 0ull;
        #pragma unroll 4
        for (int s = 0; s < 32; s++) {
            float4 k0 = *(const float4*)&Ks[s*128 + ty*8];
            float4 k1 = *(const float4*)&Ks[s*128 + ty*8 + 4];
            F4U v0, v1;
            v0.v = *(const float4*)&Vs[s*128 + tx*8];
            v1.v = *(const float4*)&Vs[s*128 + tx*8 + 4];
            float kf[8] = {k0.x,k0.y,k0.z,k0.w,k1.x,k1.y,k1.z,k1.w};
            #pragma unroll
            for (int i = 0; i < 8; i++) {
                u64 a2 = pack2(kf[i]);
                fma2(acc[i][0], a2, v0.u[0]);
                fma2(acc[i][1], a2, v0.u[1]);
                fma2(acc[i][2], a2, v1.u[0]);
                fma2(acc[i][3], a2, v1.u[1]);
            }
        }
        float* dst = g_kvp + bx*HH;
        #pragma unroll
        for (int i = 0; i < 8; i++) {
            #pragma unroll
            for (int j = 0; j < 2; j++) {
                F2U t0u, t1u; t0u.u = acc[i][j*2]; t1u.u = acc[i][j*2+1];
                *(float4*)&dst[(ty*8+i)*128 + tx*8 + j*4] =
                    make_float4(t0u.f.x, t0u.f.y, t1u.f.x, t1u.f.y);
            }
        }
    }
    gridbar();

    // ---------------- Phase S: segmented scan (2 segs x 16 chunks) -----------
    {
        __shared__ float ssum[2][128];
        __shared__ int   srst[2];
        __shared__ int   scf[NC];
        int seg = tid >> 7;            // 0..1
        int el  = tid & 127;
        int e   = bx * 128 + el;
        if (tid < NC) scf[tid] = g_crst[tid];
        __syncthreads();

        int c0 = seg * 16;
        float pre_sum[16];
        unsigned int pre_rst = 0;      // bit i = reset seen before chunk c0+i
        float run = 0.f; int rrst = 0;
        #pragma unroll
        for (int g = 0; g < 4; g++) {
            float v[4][4];
            #pragma unroll
            for (int i = 0; i < 4; i++)
                #pragma unroll
                for (int q = 0; q < 4; q++)
                    v[i][q] = g_kvp[((c0 + g*4 + i)*4 + q)*HH + e];
            #pragma unroll
            for (int i = 0; i < 4; i++) {
                int ci = g*4 + i;
                pre_sum[ci] = run;
                if (rrst) pre_rst |= (1u << ci);
                float kv = (v[i][0] + v[i][1]) + (v[i][2] + v[i][3]);
                int r = scf[c0 + ci];
                run = r ? kv : run + kv;
                rrst |= r;
            }
        }
        ssum[seg][el] = run;
        if (el == 0) srst[seg] = rrst;
        __syncthreads();

        float base = 0.f;
        if (seg == 1) base = ssum[0][el];   // (srst[0] irrelevant for base=0 start)
        int base_valid_reset = (seg == 1) ? srst[0] : 0;
        (void)base_valid_reset;
        #pragma unroll
        for (int i = 0; i < 16; i++) {
            float S = (pre_rst >> i & 1) ? pre_sum[i] : base + pre_sum[i];
            g_S[(c0 + i)*HH + e] = S;
        }
        __syncthreads();
    }
    gridbar();

    // ---------------- Phase A: attn + FF [+ map_out] -------------------------
    {
        float* bufA = sm;              // Kt -> S -> Wout
        float* bufB = sm + HH;         // V -> Wff
        float* Qs   = sm + 2*HH;       // [t][k] 32x128
        float* P    = Qs + 32*128;     // [t][s] 32x128 (later z)
        __shared__ float den_s[32];
        __shared__ int rl_s[32];

        int c  = bx >> 2;
        int tb = (bx & 3) * 32;
        int cbase = c * C;

        if (tid < 32) rl_s[tid] = g_rloc[cbase + tb + tid];
        cpW(bufA, g_kT + c*HH, tid);
        cpA(Qs, g_q + (cbase + tb)*H, tid);
        __pipeline_commit();                       // g0: Kt + Q
        cpW(bufB, g_v + cbase*H, tid);
        __pipeline_commit();                       // g1: V
        __pipeline_wait_prior(1);
        __syncthreads();

        // Stage A: P = Q @ Kt
        {
            u64 pa[4][2]; zacc(pa);
            mm32p(pa, Qs, bufA, gt, gs, 128);
            float acc[4][4]; unpk(pa, acc);
            #pragma unroll
            for (int i = 0; i < 4; i++) {
                int t_idx = gt*4 + i;
                int tl = tb + t_idx;
                int rl = rl_s[t_idx];
                int lo = (rl < 0) ? 0 : rl;
                float pr[4];
                #pragma unroll
                for (int j = 0; j < 4; j++) {
                    int s = gs*4 + j;
                    float val = acc[i][j];
                    if (s == tl) den_s[t_idx] = 1e-6f + val;
                    pr[j] = (s >= lo && s <= tl) ? val : 0.f;
                }
                *(float4*)&P[t_idx*128 + gs*4] = make_float4(pr[0],pr[1],pr[2],pr[3]);
            }
        }
        __syncthreads();
        cpW(bufA, g_S + c*HH, tid);
        __pipeline_commit();                       // g2: S -> bufA
        __pipeline_wait_prior(1);                  // g1 (V) done
        __syncthreads();

        u64 pa[4][2]; zacc(pa);
        mm32p(pa, P, bufB, gt, gs, tb + 32);       // B1: P @ V (causal bound)
        __syncthreads();
        cpW(bufB, Wff, tid);
        __pipeline_commit();                       // g3: Wff -> bufB
        __pipeline_wait_prior(1);                  // g2 (S) done
        __syncthreads();

        {   // B2: + gate * Q @ S
            float u[4];
            #pragma unroll
            for (int i = 0; i < 4; i++) u[i] = (rl_s[gt*4+i] < 0) ? 1.f : 0.f;
            #pragma unroll 16
            for (int k = 0; k < 128; k++) {
                F4U sf; sf.v = *(const float4*)&bufA[k*128 + gs*4];
                #pragma unroll
                for (int i = 0; i < 4; i++) {
                    u64 a2 = pack2(Qs[(gt*4+i)*128 + k] * u[i]);
                    fma2(pa[i][0], a2, sf.u[0]);
                    fma2(pa[i][1], a2, sf.u[1]);
                }
            }
        }

        // z = num/den + x  -> P
        {
            float acc[4][4]; unpk(pa, acc);
            #pragma unroll
            for (int i = 0; i < 4; i++) {
                int t_idx = gt*4 + i;
                int tg = cbase + tb + t_idx;
                float d = 1.f / den_s[t_idx];
                float4 xr = *(const float4*)&g_x[tg*H + gs*4];
                float4 r;
                r.x = acc[i][0]*d + xr.x; r.y = acc[i][1]*d + xr.y;
                r.z = acc[i][2]*d + xr.z; r.w = acc[i][3]*d + xr.w;
                *(float4*)&P[t_idx*128 + gs*4] = r;
            }
        }
        __syncthreads();
        if (LAST) {
            cpW(bufA, Wout, tid);
            __pipeline_commit();                   // g4: Wout -> bufA
            __pipeline_wait_prior(1);              // g3 (Wff) done
        } else {
            __pipeline_wait_prior(0);
        }
        __syncthreads();

        {   // FF: x = leaky(z @ Wff^T + bff)
            u64 pf[4][2]; zacc(pf);
            mm32p(pf, P, bufB, gt, gs, 128);
            float fa[4][4]; unpk(pf, fa);
            float4 bb = *(const float4*)&bff[gs*4];
            #pragma unroll
            for (int i = 0; i < 4; i++) {
                int tg = cbase + tb + gt*4 + i;
                float r[4] = {fa[i][0]+bb.x, fa[i][1]+bb.y, fa[i][2]+bb.z, fa[i][3]+bb.w};
                #pragma unroll
                for (int j = 0; j < 4; j++) r[j] = (r[j] > 0.f) ? r[j] : 0.01f*r[j];
                float4 rr = make_float4(r[0],r[1],r[2],r[3]);
                *(float4*)&g_x[tg*H + gs*4] = rr;
                if (LAST) *(float4*)&Qs[(gt*4+i)*128 + gs*4] = rr;
            }
        }
        if (LAST) {
            __pipeline_wait_prior(0);              // g4 (Wout) done
            __syncthreads();
            u64 pf[4][2]; zacc(pf);
            mm32p(pf, Qs, bufA, gt, gs, 128);
            float fa[4][4]; unpk(pf, fa);
            float4 bb = *(const float4*)&bout[gs*4];
            #pragma unroll
            for (int i = 0; i < 4; i++) {
                int tg = cbase + tb + gt*4 + i;
                *(float4*)&outp[tg*H + gs*4] =
                    make_float4(fa[i][0]+bb.x, fa[i][1]+bb.y, fa[i][2]+bb.z, fa[i][3]+bb.w);
            }
        }
    }
}

// ---------------- launch ------------------------------------------------------
extern "C" void kernel_launch(void* const* d_in, const int* in_sizes, int n_in,
                              void* d_out, int out_size) {
    const float* emb          = (const float*)d_in[0];
    const unsigned char* start= (const unsigned char*)d_in[1];
    const float* W_in         = (const float*)d_in[2];
    const float* b_in         = (const float*)d_in[3];
    const float* W_q          = (const float*)d_in[4];
    const float* W_k          = (const float*)d_in[5];
    const float* W_v          = (const float*)d_in[6];
    const float* W_ff         = (const float*)d_in[7];
    const float* b_ff         = (const float*)d_in[8];
    const float* W_out        = (const float*)d_in[9];
    const float* b_out        = (const float*)d_in[10];
    float* out = (float*)d_out;

    cudaFuncSetAttribute(layer_kernel<1,0>, cudaFuncAttributeMaxDynamicSharedMemorySize, SMA);
    cudaFuncSetAttribute(layer_kernel<0,1>, cudaFuncAttributeMaxDynamicSharedMemorySize, SMA);

    float *px, *pWt;
    cudaGetSymbolAddress((void**)&px, g_x);
    cudaGetSymbolAddress((void**)&pWt, g_Wt);

    prep_kernel<<<192, 256>>>(W_in, W_q, W_k, W_v, W_ff, W_out, start);

    // layer 0 (fused map_in)
    layer_kernel<1,0><<<GRID, 256, SMA>>>(emb, pWt, b_in,
                                          pWt + 1*HH, pWt + 2*HH, pWt + 3*HH,
                                          pWt + 7*HH, b_ff,
                                          nullptr, nullptr, nullptr);
    // layer 1 (fused map_out)
    layer_kernel<0,1><<<GRID, 256, SMA>>>(px, nullptr, nullptr,
                                          pWt + 4*HH, pWt + 5*HH, pWt + 6*HH,
                                          pWt + 8*HH, b_ff + H,
                                          pWt + 9*HH, b_out, out);
}

// round 14
// speedup vs baseline: 1.0818x; 1.0818x over previous
#include <cuda_runtime.h>
#include <cuda_pipeline.h>
#include <math.h>

#define T 4096
#define H 128
#define HH (H*H)
#define C 128
#define NC (T/C)   // 32
#define L 2

typedef unsigned long long u64;
union F2U { u64 u; float2 f; };
union F4U { float4 v; u64 u[2]; };

__device__ __forceinline__ u64 pack2(float a) {
    unsigned int ai = __float_as_uint(a);
    u64 r;
    asm("mov.b64 %0, {%1, %1};" : "=l"(r) : "r"(ai));
    return r;
}
__device__ __forceinline__ void fma2(u64& acc, u64 a, u64 b) {
    asm("fma.rn.f32x2 %0, %1, %2, %0;" : "+l"(acc) : "l"(a), "l"(b));
}

// ---------------- scratch (device globals; no allocation allowed) ------------
__device__ float g_x[T*H];
__device__ float g_q[T*H];
__device__ float g_k[T*H];
__device__ float g_kT[T*H];      // per-chunk transposed K: [c][k][s_local]
__device__ float g_v[T*H];
__device__ float g_Wt[10*HH];    // transposed weights [k][n]
__device__ float g_kvp[4*NC*HH]; // per-(chunk,quarter) KV partial sums
__device__ float g_S[NC*HH];     // state before each chunk
__device__ int   g_rloc[T];      // last reset index within chunk (local), -1 if none
__device__ int   g_cs0[NC];      // chunk tail-sum start (local)
__device__ int   g_crst[NC];     // chunk has reset flag

#define SMG ((2*HH + 32*128)*4)             // qkv: W0 + W1 + A tile   (144KB)
#define SMA ((2*HH + 2*32*128)*4)           // attn: bufA + bufB + Q + P (160KB)

// ---------------- prep: weight transpose + ballot-based reset preproc --------
__global__ void prep_kernel(const float* __restrict__ W_in, const float* __restrict__ W_q,
                            const float* __restrict__ W_k, const float* __restrict__ W_v,
                            const float* __restrict__ W_ff, const float* __restrict__ W_out,
                            const unsigned char* __restrict__ start) {
    int b = blockIdx.x;
    int tid = threadIdx.x;
    if (b < 160) {
        __shared__ float tile[32][33];
        int z = b >> 4, sub = b & 15;
        const float* src;
        switch (z) {
            case 0: src = W_in; break;
            case 1: src = W_q; break;
            case 2: src = W_k; break;
            case 3: src = W_v; break;
            case 4: src = W_q + HH; break;
            case 5: src = W_k + HH; break;
            case 6: src = W_v + HH; break;
            case 7: src = W_ff; break;
            case 8: src = W_ff + HH; break;
            default: src = W_out; break;
        }
        float* dst = g_Wt + z*HH;
        int k0 = (sub >> 2)*32, n0 = (sub & 3)*32;
        int tx = tid & 31, ty = tid >> 5;    // (32,8)
        #pragma unroll
        for (int i = 0; i < 4; i++)
            tile[ty + 8*i][tx] = src[(n0 + ty + 8*i)*H + k0 + tx];
        __syncthreads();
        #pragma unroll
        for (int i = 0; i < 4; i++)
            dst[(k0 + ty + 8*i)*H + n0 + tx] = tile[tx][ty + 8*i];
    } else {
        // ballot-based last-reset-index: O(4) instead of O(128) serial scan
        __shared__ unsigned mask[4];
        int c = b - 160;
        int lane = tid & 31, wid = tid >> 5;
        if (tid < 128) {
            int flag = start[c*C + tid] != 0;
            unsigned bal = __ballot_sync(0xffffffffu, flag);
            if (lane == 0) mask[wid] = bal;
        }
        __syncthreads();
        if (tid < 128) {
            int r = -1;
            #pragma unroll
            for (int w = 0; w < 4; w++) {
                unsigned m = mask[w];
                if (w < wid && m) r = w*32 + 31 - __clz(m);
            }
            unsigned lowmask = (lane == 31) ? 0xffffffffu : ((2u << lane) - 1u);
            unsigned own = mask[wid] & lowmask;
            if (own) r = wid*32 + 31 - __clz(own);
            g_rloc[c*C + tid] = r;
            if (tid == C-1) { g_cs0[c] = (r >= 0) ? r : 0; g_crst[c] = (r >= 0) ? 1 : 0; }
        }
    }
}

// ---------------- async-copy helpers -----------------------------------------
__device__ __forceinline__ void cpW(float* Ws, const float* __restrict__ Wt, int tid) {
    #pragma unroll
    for (int it = 0; it < 16; it++) {
        int idx = (tid + it*256) * 4;
        __pipeline_memcpy_async(Ws + idx, Wt + idx, 16);
    }
}
__device__ __forceinline__ void cpA(float* As, const float* __restrict__ A, int tid) {
    #pragma unroll
    for (int it = 0; it < 4; it++) {
        int idx = (tid + it*256) * 4;
        __pipeline_memcpy_async(As + idx, A + idx, 16);
    }
}

// ---------------- packed-f32x2 GEMM microkernel -------------------------------
__device__ __forceinline__ void mm32p(u64 acc[4][2], const float* As, const float* Ws,
                                      int gt, int gs, int klen) {
    #pragma unroll 16
    for (int k = 0; k < klen; k++) {
        F4U w; w.v = *(const float4*)&Ws[k*128 + gs*4];
        #pragma unroll
        for (int i = 0; i < 4; i++) {
            u64 a2 = pack2(As[(gt*4+i)*128 + k]);
            fma2(acc[i][0], a2, w.u[0]);
            fma2(acc[i][1], a2, w.u[1]);
        }
    }
}
__device__ __forceinline__ void zacc(u64 acc[4][2]) {
    #pragma unroll
    for (int i = 0; i < 4; i++) { acc[i][0] = 0ull; acc[i][1] = 0ull; }
}
__device__ __forceinline__ void unpk(const u64 acc[4][2], float o[4][4]) {
    #pragma unroll
    for (int i = 0; i < 4; i++) {
        F2U t0, t1; t0.u = acc[i][0]; t1.u = acc[i][1];
        o[i][0] = t0.f.x; o[i][1] = t0.f.y; o[i][2] = t1.f.x; o[i][3] = t1.f.y;
    }
}

__device__ __forceinline__ float phi_f(float v) {
    return (v > 0.f) ? (1.f + v) : __expf(v);
}

// ---------------- fused [map_in] + QKV (cp.async double-buffered W) ----------
template<int FIRST>
__global__ __launch_bounds__(256) void qkv_kernel(const float* __restrict__ A0,
        const float* __restrict__ Wt_in, const float* __restrict__ b_in,
        const float* __restrict__ Wtq, const float* __restrict__ Wtk,
        const float* __restrict__ Wtv) {
    extern __shared__ float sm[];
    float* W0 = sm;               // [k][n] 128x128
    float* W1 = sm + HH;
    float* As = sm + 2*HH;        // [r][k] 32x128
    int tid = threadIdx.x;
    int t0 = blockIdx.x * 32;
    int gt = tid >> 5, gs = tid & 31;

    cpA(As, A0 + t0*H, tid);
    cpW(W0, FIRST ? Wt_in : Wtq, tid);
    __pipeline_commit();                       // g0
    cpW(W1, FIRST ? Wtq : Wtk, tid);
    __pipeline_commit();                       // g1
    __pipeline_wait_prior(1);
    __syncthreads();

    if (FIRST) {   // x = emb @ W_in^T + b_in
        u64 pa[4][2]; zacc(pa);
        mm32p(pa, As, W0, gt, gs, 128);
        float acc[4][4]; unpk(pa, acc);
        __syncthreads();
        cpW(W0, Wtk, tid);
        __pipeline_commit();                   // g2: Wk -> W0
        float4 bb = *(const float4*)&b_in[gs*4];
        #pragma unroll
        for (int i = 0; i < 4; i++) {
            float4 r = make_float4(acc[i][0]+bb.x, acc[i][1]+bb.y,
                                   acc[i][2]+bb.z, acc[i][3]+bb.w);
            *(float4*)&As[(gt*4+i)*128 + gs*4] = r;
            *(float4*)&g_x[(t0 + gt*4+i)*H + gs*4] = r;
        }
        __pipeline_wait_prior(1);              // g1 (Wq) done
        __syncthreads();
        {   // q = phi(x @ Wq^T)   [W1]
            u64 p2[4][2]; zacc(p2);
            mm32p(p2, As, W1, gt, gs, 128);
            float a2[4][4]; unpk(p2, a2);
            #pragma unroll
            for (int i = 0; i < 4; i++)
                *(float4*)&g_q[(t0 + gt*4+i)*H + gs*4] =
                    make_float4(phi_f(a2[i][0]), phi_f(a2[i][1]),
                                phi_f(a2[i][2]), phi_f(a2[i][3]));
        }
        __syncthreads();                       // W1 free
        cpW(W1, Wtv, tid);
        __pipeline_commit();                   // g3: Wv -> W1
        __pipeline_wait_prior(1);              // g2 (Wk) done
        __syncthreads();
        {   // k = phi(x @ Wk^T)   [W0]
            u64 p2[4][2]; zacc(p2);
            mm32p(p2, As, W0, gt, gs, 128);
            float a2[4][4]; unpk(p2, a2);
            #pragma unroll
            for (int i = 0; i < 4; i++) {
                int t = t0 + gt*4 + i;
                float r[4] = {phi_f(a2[i][0]), phi_f(a2[i][1]),
                              phi_f(a2[i][2]), phi_f(a2[i][3])};
                *(float4*)&g_k[t*H + gs*4] = make_float4(r[0],r[1],r[2],r[3]);
                int cc = t >> 7, sl = t & 127;
                float* kT = g_kT + cc*HH + sl;
                #pragma unroll
                for (int j = 0; j < 4; j++) kT[(gs*4+j)*128] = r[j];
            }
        }
        __pipeline_wait_prior(0);              // g3 (Wv) done
        __syncthreads();
        {   // v = x @ Wv^T        [W1]
            u64 p2[4][2]; zacc(p2);
            mm32p(p2, As, W1, gt, gs, 128);
            float a2[4][4]; unpk(p2, a2);
            #pragma unroll
            for (int i = 0; i < 4; i++)
                *(float4*)&g_v[(t0 + gt*4+i)*H + gs*4] =
                    make_float4(a2[i][0], a2[i][1], a2[i][2], a2[i][3]);
        }
    } else {
        {   // q = phi(x @ Wq^T)   [W0]
            u64 p2[4][2]; zacc(p2);
            mm32p(p2, As, W0, gt, gs, 128);
            float a2[4][4]; unpk(p2, a2);
            #pragma unroll
            for (int i = 0; i < 4; i++)
                *(float4*)&g_q[(t0 + gt*4+i)*H + gs*4] =
                    make_float4(phi_f(a2[i][0]), phi_f(a2[i][1]),
                                phi_f(a2[i][2]), phi_f(a2[i][3]));
        }
        __syncthreads();                       // W0 free
        cpW(W0, Wtv, tid);
        __pipeline_commit();                   // g2: Wv -> W0
        __pipeline_wait_prior(1);              // g1 (Wk) done
        __syncthreads();
        {   // k = phi(x @ Wk^T)   [W1]
            u64 p2[4][2]; zacc(p2);
            mm32p(p2, As, W1, gt, gs, 128);
            float a2[4][4]; unpk(p2, a2);
            #pragma unroll
            for (int i = 0; i < 4; i++) {
                int t = t0 + gt*4 + i;
                float r[4] = {phi_f(a2[i][0]), phi_f(a2[i][1]),
                              phi_f(a2[i][2]), phi_f(a2[i][3])};
                *(float4*)&g_k[t*H + gs*4] = make_float4(r[0],r[1],r[2],r[3]);
                int cc = t >> 7, sl = t & 127;
                float* kT = g_kT + cc*HH + sl;
                #pragma unroll
                for (int j = 0; j < 4; j++) kT[(gs*4+j)*128] = r[j];
            }
        }
        __pipeline_wait_prior(0);              // g2 (Wv) done
        __syncthreads();
        {   // v = x @ Wv^T        [W0]
            u64 p2[4][2]; zacc(p2);
            mm32p(p2, As, W0, gt, gs, 128);
            float a2[4][4]; unpk(p2, a2);
            #pragma unroll
            for (int i = 0; i < 4; i++)
                *(float4*)&g_v[(t0 + gt*4+i)*H + gs*4] =
                    make_float4(a2[i][0], a2[i][1], a2[i][2], a2[i][3]);
        }
    }
}

// ---------------- per-chunk-quarter KV partials: g_kvp = K_q^T @ V_q ---------
__global__ __launch_bounds__(256) void chunk_kv_kernel() {
    __shared__ float Ks[32*128];
    __shared__ float Vs[32*128];
    int bx = blockIdx.x;
    int c = bx >> 2, qi = bx & 3;
    int s0 = g_cs0[c];
    int tid = threadIdx.x;
    int base = (c*C + qi*32) * H;
    {
        const float4* K4 = (const float4*)(g_k + base);
        const float4* V4 = (const float4*)(g_v + base);
        float4* Ks4 = (float4*)Ks;
        float4* Vs4 = (float4*)Vs;
        #pragma unroll
        for (int it = 0; it < 4; it++) {
            int idx = tid + it*256;
            int srow = idx >> 5;
            float4 kv4 = K4[idx];
            if (qi*32 + srow < s0) kv4 = make_float4(0.f,0.f,0.f,0.f);
            Ks4[idx] = kv4;
            Vs4[idx] = V4[idx];
        }
    }
    __syncthreads();
    int ty = tid >> 4, tx = tid & 15;
    u64 acc[8][4];
    #pragma unroll
    for (int i = 0; i < 8; i++)
        #pragma unroll
        for (int j = 0; j < 4; j++) acc[i][j] = 0ull;
    #pragma unroll 4
    for (int s = 0; s < 32; s++) {
        float4 k0 = *(const float4*)&Ks[s*128 + ty*8];
        float4 k1 = *(const float4*)&Ks[s*128 + ty*8 + 4];
        F4U v0, v1;
        v0.v = *(const float4*)&Vs[s*128 + tx*8];
        v1.v = *(const float4*)&Vs[s*128 + tx*8 + 4];
        float kf[8] = {k0.x,k0.y,k0.z,k0.w,k1.x,k1.y,k1.z,k1.w};
        #pragma unroll
        for (int i = 0; i < 8; i++) {
            u64 a2 = pack2(kf[i]);
            fma2(acc[i][0], a2, v0.u[0]);
            fma2(acc[i][1], a2, v0.u[1]);
            fma2(acc[i][2], a2, v1.u[0]);
            fma2(acc[i][3], a2, v1.u[1]);
        }
    }
    float* dst = g_kvp + bx*HH;
    #pragma unroll
    for (int i = 0; i < 8; i++) {
        #pragma unroll
        for (int j = 0; j < 2; j++) {
            F2U t0, t1; t0.u = acc[i][j*2]; t1.u = acc[i][j*2+1];
            *(float4*)&dst[(ty*8+i)*128 + tx*8 + j*4] =
                make_float4(t0.f.x, t0.f.y, t1.f.x, t1.f.y);
        }
    }
}

// ---------------- inter-chunk scan: 512 blocks x 256 threads ------------------
__global__ __launch_bounds__(256) void scan_kernel() {
    __shared__ float ssum[8][32];
    __shared__ int   srst[8];
    __shared__ int   sc[NC];
    int tid = threadIdx.x;
    int seg = tid >> 5;            // 0..7
    int el  = tid & 31;
    int e   = blockIdx.x * 32 + el;
    if (tid < NC) sc[tid] = g_crst[tid];
    __syncthreads();

    int c0 = seg * 4;
    float v[4][4];
    #pragma unroll
    for (int i = 0; i < 4; i++)
        #pragma unroll
        for (int q = 0; q < 4; q++)
            v[i][q] = g_kvp[((c0 + i)*4 + q)*HH + e];

    float kv[4];
    #pragma unroll
    for (int i = 0; i < 4; i++)
        kv[i] = (v[i][0] + v[i][1]) + (v[i][2] + v[i][3]);

    float pre_sum[4];
    int   pre_rst[4];
    float run = 0.f; int rrst = 0;
    #pragma unroll
    for (int i = 0; i < 4; i++) {
        pre_sum[i] = run; pre_rst[i] = rrst;
        int r = sc[c0 + i];
        run = r ? kv[i] : run + kv[i];
        rrst |= r;
    }
    ssum[seg][el] = run;
    if (el == 0) srst[seg] = rrst;
    __syncthreads();

    float base = 0.f;
    #pragma unroll
    for (int j = 0; j < 7; j++) {
        if (j < seg) {
            float as = ssum[j][el];
            base = srst[j] ? as : base + as;
        }
    }
    #pragma unroll
    for (int i = 0; i < 4; i++) {
        float S = pre_rst[i] ? pre_sum[i] : base + pre_sum[i];
        g_S[(c0 + i)*HH + e] = S;
    }
}

// ---------------- fused attn + FF [+ map_out] (double-buffered) ---------------
template<int LAST>
__global__ __launch_bounds__(256) void attn_ff_kernel(
        const float* __restrict__ Wff, const float* __restrict__ bff,
        const float* __restrict__ Wout, const float* __restrict__ bout,
        float* __restrict__ outp) {
    extern __shared__ float sm[];
    float* bufA = sm;              // 128x128: Kt -> S -> Wout
    float* bufB = sm + HH;         // 128x128: V -> Wff
    float* Qs   = sm + 2*HH;       // [t][k] 32x128
    float* P    = Qs + 32*128;     // [t][s] 32x128 (later z tile)
    __shared__ float den_s[32];
    __shared__ int rl_s[32];

    int bx = blockIdx.x;
    int c  = bx >> 2;
    int tb = (bx & 3) * 32;
    int cbase = c * C;
    int tid = threadIdx.x;
    int gt = tid >> 5, gs = tid & 31;

    if (tid < 32) rl_s[tid] = g_rloc[cbase + tb + tid];
    cpW(bufA, g_kT + c*HH, tid);
    cpA(Qs, g_q + (cbase + tb)*H, tid);
    __pipeline_commit();                       // g0: Kt + Q
    cpW(bufB, g_v + cbase*H, tid);
    __pipeline_commit();                       // g1: V
    __pipeline_wait_prior(1);
    __syncthreads();

    // Stage A: P[t][s] = q_t . k_s   [bufA = Kt]
    {
        u64 pa[4][2]; zacc(pa);
        mm32p(pa, Qs, bufA, gt, gs, 128);
        float acc[4][4]; unpk(pa, acc);
        #pragma unroll
        for (int i = 0; i < 4; i++) {
            int t_idx = gt*4 + i;
            int tl = tb + t_idx;
            int rl = rl_s[t_idx];
            int lo = (rl < 0) ? 0 : rl;
            float pr[4];
            #pragma unroll
            for (int j = 0; j < 4; j++) {
                int s = gs*4 + j;
                float val = acc[i][j];
                if (s == tl) den_s[t_idx] = 1e-6f + val;
                pr[j] = (s >= lo && s <= tl) ? val : 0.f;
            }
            *(float4*)&P[t_idx*128 + gs*4] = make_float4(pr[0],pr[1],pr[2],pr[3]);
        }
    }
    __syncthreads();                           // bufA free, P published
    cpW(bufA, g_S + c*HH, tid);
    __pipeline_commit();                       // g2: S -> bufA
    __pipeline_wait_prior(1);                  // g1 (V) done
    __syncthreads();

    u64 pa[4][2]; zacc(pa);
    mm32p(pa, P, bufB, gt, gs, tb + 32);       // B1: P @ V [bufB], causal bound
    __syncthreads();                           // bufB free
    cpW(bufB, Wff, tid);
    __pipeline_commit();                       // g3: Wff -> bufB
    __pipeline_wait_prior(1);                  // g2 (S) done
    __syncthreads();

    {   // B2: + gate * Q @ S   [bufA]
        float u[4];
        #pragma unroll
        for (int i = 0; i < 4; i++) u[i] = (rl_s[gt*4+i] < 0) ? 1.f : 0.f;
        #pragma unroll 16
        for (int k = 0; k < 128; k++) {
            F4U sf; sf.v = *(const float4*)&bufA[k*128 + gs*4];
            #pragma unroll
            for (int i = 0; i < 4; i++) {
                u64 a2 = pack2(Qs[(gt*4+i)*128 + k] * u[i]);
                fma2(pa[i][0], a2, sf.u[0]);
                fma2(pa[i][1], a2, sf.u[1]);
            }
        }
    }

    // z = num/den + x  -> P
    {
        float acc[4][4]; unpk(pa, acc);
        #pragma unroll
        for (int i = 0; i < 4; i++) {
            int t_idx = gt*4 + i;
            int tg = cbase + tb + t_idx;
            float d = 1.f / den_s[t_idx];
            float4 xr = *(const float4*)&g_x[tg*H + gs*4];
            float4 r;
            r.x = acc[i][0]*d + xr.x; r.y = acc[i][1]*d + xr.y;
            r.z = acc[i][2]*d + xr.z; r.w = acc[i][3]*d + xr.w;
            *(float4*)&P[t_idx*128 + gs*4] = r;
        }
    }
    __syncthreads();                           // bufA free, z published
    if (LAST) {
        cpW(bufA, Wout, tid);
        __pipeline_commit();                   // g4: Wout -> bufA
        __pipeline_wait_prior(1);              // g3 (Wff) done
    } else {
        __pipeline_wait_prior(0);
    }
    __syncthreads();

    {   // FF: x = leaky(z @ Wff^T + bff)   [bufB]
        u64 pf[4][2]; zacc(pf);
        mm32p(pf, P, bufB, gt, gs, 128);
        float fa[4][4]; unpk(pf, fa);
        float4 bb = *(const float4*)&bff[gs*4];
        #pragma unroll
        for (int i = 0; i < 4; i++) {
            int tg = cbase + tb + gt*4 + i;
            float r[4] = {fa[i][0]+bb.x, fa[i][1]+bb.y, fa[i][2]+bb.z, fa[i][3]+bb.w};
            #pragma unroll
            for (int j = 0; j < 4; j++) r[j] = (r[j] > 0.f) ? r[j] : 0.01f*r[j];
            float4 rr = make_float4(r[0],r[1],r[2],r[3]);
            *(float4*)&g_x[tg*H + gs*4] = rr;
            if (LAST) *(float4*)&Qs[(gt*4+i)*128 + gs*4] = rr;
        }
    }
    if (LAST) {
        __pipeline_wait_prior(0);              // g4 (Wout) done
        __syncthreads();                       // x tile published in Qs
        u64 pf[4][2]; zacc(pf);
        mm32p(pf, Qs, bufA, gt, gs, 128);
        float fa[4][4]; unpk(pf, fa);
        float4 bb = *(const float4*)&bout[gs*4];
        #pragma unroll
        for (int i = 0; i < 4; i++) {
            int tg = cbase + tb + gt*4 + i;
            *(float4*)&outp[tg*H + gs*4] =
                make_float4(fa[i][0]+bb.x, fa[i][1]+bb.y, fa[i][2]+bb.z, fa[i][3]+bb.w);
        }
    }
}

// ---------------- launch ------------------------------------------------------
extern "C" void kernel_launch(void* const* d_in, const int* in_sizes, int n_in,
                              void* d_out, int out_size) {
    const float* emb          = (const float*)d_in[0];
    const unsigned char* start= (const unsigned char*)d_in[1];
    const float* W_in         = (const float*)d_in[2];
    const float* b_in         = (const float*)d_in[3];
    const float* W_q          = (const float*)d_in[4];
    const float* W_k          = (const float*)d_in[5];
    const float* W_v          = (const float*)d_in[6];
    const float* W_ff         = (const float*)d_in[7];
    const float* b_ff         = (const float*)d_in[8];
    const float* W_out        = (const float*)d_in[9];
    const float* b_out        = (const float*)d_in[10];
    float* out = (float*)d_out;

    cudaFuncSetAttribute(qkv_kernel<1>, cudaFuncAttributeMaxDynamicSharedMemorySize, SMG);
    cudaFuncSetAttribute(qkv_kernel<0>, cudaFuncAttributeMaxDynamicSharedMemorySize, SMG);
    cudaFuncSetAttribute(attn_ff_kernel<0>, cudaFuncAttributeMaxDynamicSharedMemorySize, SMA);
    cudaFuncSetAttribute(attn_ff_kernel<1>, cudaFuncAttributeMaxDynamicSharedMemorySize, SMA);

    float *px, *pWt;
    cudaGetSymbolAddress((void**)&px, g_x);
    cudaGetSymbolAddress((void**)&pWt, g_Wt);

    prep_kernel<<<192, 256>>>(W_in, W_q, W_k, W_v, W_ff, W_out, start);

    // layer 0 (fused map_in)
    qkv_kernel<1><<<T/32, 256, SMG>>>(emb, pWt, b_in,
                                      pWt + 1*HH, pWt + 2*HH, pWt + 3*HH);
    chunk_kv_kernel<<<NC*4, 256>>>();
    scan_kernel<<<512, 256>>>();
    attn_ff_kernel<0><<<NC*4, 256, SMA>>>(pWt + 7*HH, b_ff, nullptr, nullptr, nullptr);

    // layer 1 (fused map_out)
    qkv_kernel<0><<<T/32, 256, SMG>>>(px, nullptr, nullptr,
                                      pWt + 4*HH, pWt + 5*HH, pWt + 6*HH);
    chunk_kv_kernel<<<NC*4, 256>>>();
    scan_kernel<<<512, 256>>>();
    attn_ff_kernel<1><<<NC*4, 256, SMA>>>(pWt + 8*HH, b_ff + H,
                                          pWt + 9*HH, b_out, out);
}